// round 13
// baseline (speedup 1.0000x reference)
#include <cuda_runtime.h>
#include <cooperative_groups.h>
#include <stdint.h>
namespace cg = cooperative_groups;

#define NN 50000
#define L1N 25000
#define L2N 12500
#define L3N 6250
#define EE 800000
#define HD 128
#define BNS 0.9999950000374997f
#define GRID_COOP 296

static inline int cdiv(int a, int b){ return (a + b - 1) / b; }

// ------------------------- device scratch (static, no allocs) -------------------------
__device__ float g_h0[(size_t)NN*HD];
__device__ float g_h1[(size_t)L1N*HD];
__device__ float g_h2[(size_t)L2N*HD];
__device__ float g_w [(size_t)NN*HD];
__device__ float g_o [(size_t)NN*HD];
__device__ float g_bb[(size_t)NN*HD];
__device__ float g_ew0[EE];
__device__ int4  g_eint[3][EE];   // compacted edges per child level: {a, b, wbits, 0}
__device__ int4  g_ecsr[4][EE];   // CSR per level: {src, c1bits, c2bits, 0}
__device__ int   g_rp0[NN+1];
__device__ int   g_rp1[L1N+1];
__device__ int   g_rp2[L2N+1];
__device__ int   g_rp3[L3N+1];
__device__ int   g_cur[NN];
__device__ int   g_cnt[NN];
__device__ int   g_bsum[64];
__device__ float g_dv1[NN];
__device__ float g_dv2[NN];
__device__ float g_deg0[NN];
__device__ float g_deg1[L1N];
__device__ float g_deg2[L2N];
__device__ float g_deg3[L3N];
__device__ float g_s[NN];
__device__ unsigned g_u[NN];
__device__ int g_perm1[L1N];
__device__ int g_perm2[L2N];
__device__ int g_perm3[L3N];
__device__ int g_pos1[NN];
__device__ int g_pos2[L1N];
__device__ int g_pos3[L2N];
__device__ unsigned g_hist0[2048];
__device__ unsigned g_hist1[2048];
__device__ unsigned g_hist2[1024];
__device__ unsigned g_mn, g_mx;
__device__ unsigned g_thr;
__device__ int g_T;
__device__ unsigned g_selP;
__device__ int g_selK;
__device__ int g_pcnt, g_eqcnt;
__device__ int g_ecnt[3];
__device__ float g_gsum[HD];

// ------------------------- helpers -------------------------
__device__ __forceinline__ unsigned fenc(float f){
    unsigned u = __float_as_uint(f);
    return (u & 0x80000000u) ? ~u : (u | 0x80000000u);
}
__device__ __forceinline__ float fdec(unsigned u){
    return __uint_as_float((u & 0x80000000u) ? (u ^ 0x80000000u) : ~u);
}
__device__ __forceinline__ unsigned long long dup2(float x){
    unsigned long long r; unsigned u = __float_as_uint(x);
    asm("mov.b64 %0, {%1, %1};" : "=l"(r) : "r"(u));
    return r;
}
#define FMA2(d, a, b) asm("fma.rn.f32x2 %0, %1, %2, %0;" : "+l"(d) : "l"(a), "l"(b))
__device__ __forceinline__ float lrelu1(float v){ return v > 0.f ? v : 0.01f * v; }
__device__ __forceinline__ float4 lrelu4(float4 v){
    v.x = lrelu1(v.x); v.y = lrelu1(v.y); v.z = lrelu1(v.z); v.w = lrelu1(v.w);
    return v;
}

// ------------------------- scan phases (shared by mega kernels) -------------------------
__device__ void scanA_phase(int kn, int* sm){
    int tid = threadIdx.x, bid = blockIdx.x;
    int ntiles = (kn + 1023) >> 10;
    if (bid >= ntiles) return;
    int base = bid * 1024 + tid * 4;
    int s = 0;
    if (base + 3 < kn){
        int4 v = *(const int4*)&g_cnt[base];
        s = v.x + v.y + v.z + v.w;
    } else {
        #pragma unroll
        for (int j = 0; j < 4; j++) if (base + j < kn) s += g_cnt[base + j];
    }
    #pragma unroll
    for (int off = 16; off > 0; off >>= 1) s += __shfl_xor_sync(0xffffffffu, s, off);
    if ((tid & 31) == 0) sm[tid >> 5] = s;
    __syncthreads();
    if (tid == 0){
        int t = 0;
        #pragma unroll
        for (int j = 0; j < 8; j++) t += sm[j];
        g_bsum[bid] = t;
    }
}

__device__ void scanB_phase(const float* __restrict__ deg, int kn, int* __restrict__ rp,
                            int* sm){
    int tid = threadIdx.x, bid = blockIdx.x;
    int ntiles = (kn + 1023) >> 10;
    if (bid >= ntiles) return;
    int lane = tid & 31, w = tid >> 5;
    int v = (tid < 64 && tid < bid) ? g_bsum[tid] : 0;
    if (tid < 64){
        #pragma unroll
        for (int off = 16; off > 0; off >>= 1) v += __shfl_xor_sync(0xffffffffu, v, off);
        if (lane == 0) sm[8 + w] = v;
    }
    __syncthreads();
    int sOff = sm[8] + sm[9];
    int base = bid * 1024 + tid * 4;
    int a0 = 0, a1 = 0, a2 = 0, a3 = 0;
    if (base + 3 < kn){
        int4 t4 = *(const int4*)&g_cnt[base];
        a0 = t4.x; a1 = t4.y; a2 = t4.z; a3 = t4.w;
    } else {
        if (base     < kn) a0 = g_cnt[base];
        if (base + 1 < kn) a1 = g_cnt[base + 1];
        if (base + 2 < kn) a2 = g_cnt[base + 2];
        if (base + 3 < kn) a3 = g_cnt[base + 3];
    }
    int tsum = a0 + a1 + a2 + a3;
    int x = tsum;
    #pragma unroll
    for (int off = 1; off < 32; off <<= 1){
        int t = __shfl_up_sync(0xffffffffu, x, off);
        if (lane >= off) x += t;
    }
    if (lane == 31) sm[16 + w] = x;
    __syncthreads();
    if (tid < 32){
        int y = (tid < 8) ? sm[16 + tid] : 0;
        #pragma unroll
        for (int off = 1; off < 32; off <<= 1){
            int t = __shfl_up_sync(0xffffffffu, y, off);
            if (tid >= off) y += t;
        }
        if (tid < 8) sm[16 + tid] = y;
    }
    __syncthreads();
    int running = sOff + (x - tsum) + ((w > 0) ? sm[16 + w - 1] : 0);
    int av[4] = { a0, a1, a2, a3 };
    #pragma unroll
    for (int j = 0; j < 4; j++){
        int i = base + j;
        if (i < kn){
            rp[i] = running;
            g_cur[i] = running;
            float dg = deg[i];
            g_dv1[i] = rsqrtf(dg + 1.f);
            g_dv2[i] = rsqrtf(dg + 2.f);
            running += av[j];
            if (i == kn - 1) rp[kn] = running;
        }
    }
}

// ------------------------- mega0: init+ew+ewfin+scan+fill (cooperative) ---------------
__global__ void __launch_bounds__(256) k_mega0(
        const float* __restrict__ ea, const float* __restrict__ ww,
        const float* __restrict__ wb, const int* __restrict__ src0,
        const int* __restrict__ dst0, int* __restrict__ rp){
    cg::grid_group grid = cg::this_grid();
    __shared__ unsigned sh[2048];
    int tid = threadIdx.x, bid = blockIdx.x;
    int gs = gridDim.x * blockDim.x, gtid = bid * blockDim.x + tid;

    // P0: zero everything needed downstream
    for (int i = gtid; i < 2048; i += gs){ g_hist0[i] = 0u; g_hist1[i] = 0u; }
    for (int i = gtid; i < 1024; i += gs) g_hist2[i] = 0u;
    for (int i = gtid; i < NN; i += gs){ g_deg0[i] = 0.f; g_cnt[i] = 0; }
    for (int i = gtid; i < HD; i += gs) g_gsum[i] = 0.f;
    if (gtid == 0){ g_mn = 0xFFFFFFFFu; g_mx = 0u; }
    grid.sync();

    // P1: edge embedding + min/max
    {
        float wb0 = wb[0];
        const float4* w4 = (const float4*)ww;
        float4 wv0 = w4[0], wv1 = w4[1], wv2 = w4[2], wv3 = w4[3];
        unsigned umn = 0xFFFFFFFFu, umx = 0u;
        for (int e = gtid; e < EE; e += gs){
            const float4* a4 = (const float4*)(ea + (size_t)e * 16);
            float4 a0 = a4[0], a1 = a4[1], a2 = a4[2], a3 = a4[3];
            float acc = wb0
                + a0.x*wv0.x + a0.y*wv0.y + a0.z*wv0.z + a0.w*wv0.w
                + a1.x*wv1.x + a1.y*wv1.y + a1.z*wv1.z + a1.w*wv1.w
                + a2.x*wv2.x + a2.y*wv2.y + a2.z*wv2.z + a2.w*wv2.w
                + a3.x*wv3.x + a3.y*wv3.y + a3.z*wv3.z + a3.w*wv3.w;
            g_ew0[e] = acc;
            unsigned u = fenc(acc);
            umn = min(umn, u); umx = max(umx, u);
        }
        sh[tid] = umn; sh[256 + tid] = umx;
        __syncthreads();
        for (int s = 128; s > 0; s >>= 1){
            if (tid < s){
                sh[tid] = min(sh[tid], sh[tid + s]);
                sh[256 + tid] = max(sh[256 + tid], sh[256 + tid + s]);
            }
            __syncthreads();
        }
        if (tid == 0){ atomicMin(&g_mn, sh[0]); atomicMax(&g_mx, sh[256]); }
    }
    grid.sync();

    // P2: normalize + level-0 degree + counts
    {
        float mn = fdec(g_mn), mx = fdec(g_mx);
        float inv = 1.f / ((mx - mn) + 1e-7f);
        for (int e = gtid; e < EE; e += gs){
            float w2 = (g_ew0[e] - mn) * inv;
            g_ew0[e] = w2;
            int d = dst0[e];
            atomicAdd(&g_deg0[d], w2);
            atomicAdd(&g_cnt[d], 1);
        }
    }
    grid.sync();
    scanA_phase(NN, (int*)sh);
    grid.sync();
    scanB_phase(g_deg0, NN, rp, (int*)sh);
    grid.sync();
    // P5: CSR fill (level 0) — single 16B store per edge
    for (int e = gtid; e < EE; e += gs){
        int a = src0[e], b = dst0[e];
        float we = g_ew0[e];
        int slot = atomicAdd(&g_cur[b], 1);
        g_ecsr[0][slot] = make_int4(a,
            __float_as_int(g_dv1[a] * we * g_dv1[b]),
            __float_as_int(g_dv2[a] * we * g_dv2[b]), 0);
    }
}

// ------------------------- radix-select helper -------------------------
__device__ __forceinline__ void warp_sel(const unsigned* A, int nbins, int k,
                                         unsigned* outBin, int* outKrem){
    int lane = threadIdx.x & 31;
    int chunk = nbins >> 5;
    int base = nbins - 1 - lane * chunk;
    unsigned cnt = 0;
    for (int j = 0; j < chunk; j++) cnt += A[base - j];
    unsigned pre = cnt;
    #pragma unroll
    for (int off = 1; off < 32; off <<= 1){
        unsigned t = __shfl_up_sync(0xffffffffu, pre, off);
        if (lane >= off) pre += t;
    }
    pre -= cnt;
    bool sel = (pre < (unsigned)k) && ((unsigned)k <= pre + cnt);
    unsigned m = __ballot_sync(0xffffffffu, sel);
    int L = __ffs(m) - 1;
    unsigned bin = 0; int krem = 0;
    if (lane == L){
        unsigned run = pre;
        for (int j = 0; j < chunk; j++){
            int b = base - j;
            unsigned c = A[b];
            if (run + c >= (unsigned)k){ bin = (unsigned)b; krem = k - (int)run; break; }
            run += c;
        }
    }
    bin  = __shfl_sync(0xffffffffu, bin, L);
    krem = __shfl_sync(0xffffffffu, krem, L);
    *outBin = bin; *outKrem = krem;
}

// ------------------------- mega level: grid-wide 3-pass select + partition + ... ------
__global__ void __launch_bounds__(256) k_mega(int n, int k,
        const int* __restrict__ s, const int* __restrict__ d, const float* __restrict__ w,
        const int4* __restrict__ ein,
        int fixedcnt, const int* __restrict__ dyncnt,
        int* __restrict__ perm, int* __restrict__ pos, float* __restrict__ degn,
        int* __restrict__ ecnt,
        int4* __restrict__ eout, int4* __restrict__ ecsr,
        int* __restrict__ rp){
    cg::grid_group grid = cg::this_grid();
    __shared__ unsigned sh[2048];
    int tid = threadIdx.x, bid = blockIdx.x;
    int gs = gridDim.x * blockDim.x, gtid = bid * blockDim.x + tid;

    // S0: grid-wide pass-0 histogram -> g_hist0 (pre-zeroed)
    for (int i = tid; i < 2048; i += 256) sh[i] = 0u;
    __syncthreads();
    for (int i = gtid; i < n; i += gs) atomicAdd(&sh[g_u[i] >> 21], 1u);
    __syncthreads();
    for (int i = tid; i < 2048; i += 256){
        unsigned c = sh[i];
        if (c) atomicAdd(&g_hist0[i], c);
    }
    grid.sync();

    // S1: block0 select pass 0
    if (bid == 0 && tid < 32){
        unsigned b; int kr;
        warp_sel(g_hist0, 2048, k, &b, &kr);
        if (tid == 0){ g_selP = b; g_selK = kr; }
    }
    grid.sync();

    // S2: grid-wide pass-1 histogram -> g_hist1 ; zero g_hist0
    {
        unsigned p0 = g_selP;
        for (int i = tid; i < 2048; i += 256) sh[i] = 0u;
        __syncthreads();
        for (int i = gtid; i < n; i += gs){
            unsigned ui = g_u[i];
            if ((ui >> 21) == p0) atomicAdd(&sh[(ui >> 10) & 2047u], 1u);
        }
        __syncthreads();
        for (int i = tid; i < 2048; i += 256){
            unsigned c = sh[i];
            if (c) atomicAdd(&g_hist1[i], c);
        }
        for (int i = gtid; i < 2048; i += gs) g_hist0[i] = 0u;
    }
    grid.sync();

    // S3: block0 select pass 1
    if (bid == 0 && tid < 32){
        unsigned p0 = g_selP;
        unsigned b; int kr;
        warp_sel(g_hist1, 2048, g_selK, &b, &kr);
        if (tid == 0){ g_selP = (p0 << 11) | b; g_selK = kr; }
    }
    grid.sync();

    // S4: grid-wide pass-2 histogram -> g_hist2 ; zero g_hist1
    {
        unsigned p1 = g_selP;
        for (int i = tid; i < 1024; i += 256) sh[i] = 0u;
        __syncthreads();
        for (int i = gtid; i < n; i += gs){
            unsigned ui = g_u[i];
            if ((ui >> 10) == p1) atomicAdd(&sh[ui & 1023u], 1u);
        }
        __syncthreads();
        for (int i = tid; i < 1024; i += 256){
            unsigned c = sh[i];
            if (c) atomicAdd(&g_hist2[i], c);
        }
        for (int i = gtid; i < 2048; i += gs) g_hist1[i] = 0u;
    }
    grid.sync();

    // S5: block0 select pass 2 -> threshold + reset counters
    if (bid == 0 && tid < 32){
        unsigned p1 = g_selP;
        unsigned b; int kr;
        warp_sel(g_hist2, 1024, g_selK, &b, &kr);
        if (tid == 0){
            g_thr = (p1 << 10) | b; g_T = kr;
            g_pcnt = 0; g_eqcnt = 0; *ecnt = 0;
        }
    }
    grid.sync();

    // P3: partition + zero child deg/cnt + zero g_hist2 for next level
    {
        unsigned ut = g_thr; int T = g_T;
        for (int i = gtid; i < 1024; i += gs) g_hist2[i] = 0u;
        for (int i = gtid; i < k; i += gs){ degn[i] = 0.f; g_cnt[i] = 0; }
        for (int i = gtid; i < n; i += gs){
            unsigned ui = g_u[i];
            int p = -1;
            if (ui > ut) p = atomicAdd(&g_pcnt, 1);
            else if (ui == ut){
                int t = atomicAdd(&g_eqcnt, 1);
                if (t < T) p = atomicAdd(&g_pcnt, 1);
            }
            pos[i] = p;
            if (p >= 0) perm[p] = i;
        }
    }
    grid.sync();

    // P4: relabel (compact valid edges as int4 + child degree/count)
    {
        int cntE = dyncnt ? *dyncnt : fixedcnt;
        for (int e = gtid; e < cntE; e += gs){
            int a, b2; float we;
            if (ein){
                int4 m = ein[e];
                a = pos[m.x]; b2 = pos[m.y]; we = __int_as_float(m.z);
            } else {
                a = pos[s[e]]; b2 = pos[d[e]]; we = w[e];
            }
            if (a >= 0 && b2 >= 0){
                int j = atomicAdd(ecnt, 1);
                eout[j] = make_int4(a, b2, __float_as_int(we), 0);
                atomicAdd(&degn[b2], we);
                atomicAdd(&g_cnt[b2], 1);
            }
        }
    }
    grid.sync();
    scanA_phase(k, (int*)sh);
    grid.sync();
    scanB_phase(degn, k, rp, (int*)sh);
    grid.sync();
    // S7: CSR fill (child) — single 16B store per edge
    {
        int cE = *ecnt;
        for (int e = gtid; e < cE; e += gs){
            int4 m = eout[e];
            int a = m.x, b2 = m.y;
            float we = __int_as_float(m.z);
            int slot = atomicAdd(&g_cur[b2], 1);
            ecsr[slot] = make_int4(a,
                __float_as_int(g_dv1[a] * we * g_dv1[b2]),
                __float_as_int(g_dv2[a] * we * g_dv2[b2]), 0);
        }
    }
}

// ------------------------- fused GEMM (writes C only) -------------------------
__global__ void __launch_bounds__(256, 2) k_mm(
        const float* __restrict__ A, const float* __restrict__ W,
        float* __restrict__ C,
        const float* __restrict__ bns, const float* __restrict__ bnb,
        const int* __restrict__ perm,
        const int* __restrict__ pos, const float* __restrict__ uu, int uflag, int n){
    __shared__ __align__(16) float As[16][132];
    __shared__ __align__(16) float Bs[16][128];
    int tid = threadIdx.x;
    int tx = tid & 15, ty = tid >> 4;
    int bm0 = blockIdx.x * 128;
    unsigned long long acc[4][8];
    #pragma unroll
    for (int p = 0; p < 4; p++)
        #pragma unroll
        for (int c = 0; c < 8; c++) acc[p][c] = 0ull;

    for (int k0 = 0; k0 < 128; k0 += 16){
        #pragma unroll
        for (int i = 0; i < 2; i++){
            int idx = tid + i * 256;
            int r = idx >> 2, c4 = idx & 3;
            int grow = bm0 + r;
            float4 v = make_float4(0.f, 0.f, 0.f, 0.f);
            if (grow < n){
                if (perm){
                    int old = perm[grow];
                    v = lrelu4(*(const float4*)(A + (size_t)old * 128 + k0 + c4 * 4));
                    float sc = g_s[old];
                    float4 s4 = *(const float4*)(bns + k0 + c4 * 4);
                    float4 o4 = *(const float4*)(bnb + k0 + c4 * 4);
                    v.x = v.x * sc * (s4.x * BNS) + o4.x;
                    v.y = v.y * sc * (s4.y * BNS) + o4.y;
                    v.z = v.z * sc * (s4.z * BNS) + o4.z;
                    v.w = v.w * sc * (s4.w * BNS) + o4.w;
                } else if (pos){
                    v = lrelu4(*(const float4*)(A + (size_t)grow * 128 + k0 + c4 * 4));
                    int pr = pos[grow];
                    if (pr >= 0){
                        float4 uv = *(const float4*)(uu + (size_t)pr * 128 + k0 + c4 * 4);
                        if (uflag) uv = lrelu4(uv);
                        v.x += uv.x; v.y += uv.y; v.z += uv.z; v.w += uv.w;
                    }
                } else {
                    v = *(const float4*)(A + (size_t)grow * 128 + k0 + c4 * 4);
                    if (bns){
                        float4 s4 = *(const float4*)(bns + k0 + c4 * 4);
                        float4 o4 = *(const float4*)(bnb + k0 + c4 * 4);
                        v.x = v.x * (s4.x * BNS) + o4.x;
                        v.y = v.y * (s4.y * BNS) + o4.y;
                        v.z = v.z * (s4.z * BNS) + o4.z;
                        v.w = v.w * (s4.w * BNS) + o4.w;
                    }
                }
            }
            As[c4*4+0][r] = v.x; As[c4*4+1][r] = v.y;
            As[c4*4+2][r] = v.z; As[c4*4+3][r] = v.w;
        }
        #pragma unroll
        for (int i = 0; i < 2; i++){
            int idx = tid + i * 256;
            int kk = idx >> 5, c = idx & 31;
            *(float4*)&Bs[kk][c*4] = *(const float4*)(W + (size_t)(k0 + kk) * 128 + c * 4);
        }
        __syncthreads();
        #pragma unroll
        for (int kk = 0; kk < 16; kk++){
            ulonglong2 aA = *(const ulonglong2*)&As[kk][ty*8];
            ulonglong2 aB = *(const ulonglong2*)&As[kk][ty*8+4];
            float4 b0 = *(const float4*)&Bs[kk][tx*8];
            float4 b1 = *(const float4*)&Bs[kk][tx*8+4];
            unsigned long long ap[4] = { aA.x, aA.y, aB.x, aB.y };
            unsigned long long bb[8] = { dup2(b0.x), dup2(b0.y), dup2(b0.z), dup2(b0.w),
                                         dup2(b1.x), dup2(b1.y), dup2(b1.z), dup2(b1.w) };
            #pragma unroll
            for (int p = 0; p < 4; p++)
                #pragma unroll
                for (int c = 0; c < 8; c++)
                    FMA2(acc[p][c], ap[p], bb[c]);
        }
        __syncthreads();
    }
    #pragma unroll
    for (int p = 0; p < 4; p++){
        #pragma unroll
        for (int j = 0; j < 2; j++){
            int row = bm0 + ty*8 + 2*p + j;
            if (row >= n) continue;
            float vals[8];
            #pragma unroll
            for (int c = 0; c < 8; c++){
                unsigned long long u = acc[p][c];
                vals[c] = j ? __uint_as_float((unsigned)(u >> 32))
                            : __uint_as_float((unsigned)u);
            }
            *(float4*)(C + (size_t)row * 128 + tx*8)     =
                make_float4(vals[0], vals[1], vals[2], vals[3]);
            *(float4*)(C + (size_t)row * 128 + tx*8 + 4) =
                make_float4(vals[4], vals[5], vals[6], vals[7]);
        }
    }
}

// ------------- CSR gather (int4 edges) + self-loop epilogue (+ fused score) -----------
__global__ void k_gather(const int* __restrict__ rp, const int4* __restrict__ ecsr,
                         int useC2, const float* __restrict__ C,
                         float* __restrict__ out, int n, const float* __restrict__ p,
                         const float* __restrict__ bias, const float* __restrict__ deg,
                         float fill){
    int wid = (blockIdx.x * blockDim.x + threadIdx.x) >> 5;
    int lane = threadIdx.x & 31;
    if (wid >= n) return;
    int beg = rp[wid], end = rp[wid + 1];
    float4 acc = make_float4(0.f, 0.f, 0.f, 0.f);
    int e = beg;
    for (; e + 1 < end; e += 2){
        int4 m0 = ecsr[e], m1 = ecsr[e+1];
        float c0 = __int_as_float(useC2 ? m0.z : m0.y);
        float c1 = __int_as_float(useC2 ? m1.z : m1.y);
        float4 v0 = *(const float4*)(C + (size_t)m0.x * 128 + lane * 4);
        float4 v1 = *(const float4*)(C + (size_t)m1.x * 128 + lane * 4);
        acc.x += c0*v0.x + c1*v1.x;
        acc.y += c0*v0.y + c1*v1.y;
        acc.z += c0*v0.z + c1*v1.z;
        acc.w += c0*v0.w + c1*v1.w;
    }
    if (e < end){
        int4 m0 = ecsr[e];
        float c0 = __int_as_float(useC2 ? m0.z : m0.y);
        float4 v0 = *(const float4*)(C + (size_t)m0.x * 128 + lane * 4);
        acc.x += c0*v0.x; acc.y += c0*v0.y; acc.z += c0*v0.z; acc.w += c0*v0.w;
    }
    float4 cr = *(const float4*)(C + (size_t)wid * 128 + lane * 4);
    float sc = fill / (deg[wid] + fill);
    float4 b4 = *(const float4*)(bias + lane * 4);
    float4 o;
    o.x = acc.x + sc * cr.x + b4.x;
    o.y = acc.y + sc * cr.y + b4.y;
    o.z = acc.z + sc * cr.z + b4.z;
    o.w = acc.w + sc * cr.w + b4.w;
    *(float4*)(out + (size_t)wid * 128 + lane * 4) = o;
    if (p){
        float4 pv = *(const float4*)(p + lane * 4);
        float4 hv = lrelu4(o);
        float d = hv.x*pv.x + hv.y*pv.y + hv.z*pv.z + hv.w*pv.w;
        float pp = pv.x*pv.x + pv.y*pv.y + pv.z*pv.z + pv.w*pv.w;
        #pragma unroll
        for (int off = 16; off > 0; off >>= 1){
            d  += __shfl_xor_sync(0xffffffffu, d, off);
            pp += __shfl_xor_sync(0xffffffffu, pp, off);
        }
        if (lane == 0){
            float v = tanhf(d / sqrtf(pp));
            g_s[wid] = v;
            g_u[wid] = fenc(v);
        }
    }
}

// ------------------------- readout -------------------------
__global__ void k_colsum(const float* __restrict__ h, int n){
    int d = threadIdx.x;
    int r0 = blockIdx.x * 256;
    int rend = min(r0 + 256, n);
    float acc = 0.f;
    for (int r = r0; r < rend; r++) acc += h[(size_t)r * 128 + d];
    atomicAdd(&g_gsum[d], acc);
}

__global__ void k_final(const float* __restrict__ Wr, const float* __restrict__ br,
                        const float* __restrict__ gr, const float* __restrict__ brn,
                        float* __restrict__ out, int osz){
    __shared__ float gs[HD];
    int t = threadIdx.x;
    gs[t] = g_gsum[t];
    __syncthreads();
    float acc = br[t];
    for (int d2 = 0; d2 < HD; d2++) acc += gs[d2] * Wr[d2 * HD + t];
    float r = acc * (gr[t] * BNS) + brn[t];
    if (t < osz) out[t] = r;
}

// ------------------------- host orchestration -------------------------
extern "C" void kernel_launch(void* const* d_in, const int* in_sizes, int n_in,
                              void* d_out, int out_size){
    const float* x   = (const float*)d_in[0];
    const int*   ei  = (const int*)d_in[1];
    const float* ea  = (const float*)d_in[2];
    const float* Wew = (const float*)d_in[3];
    const float* Web = (const float*)d_in[4];
    const float* Wd  = (const float*)d_in[5];
    const float* bd  = (const float*)d_in[6];
    const float* Wp  = (const float*)d_in[7];
    const float* Wu  = (const float*)d_in[8];
    const float* bu  = (const float*)d_in[9];
    const float* gn  = (const float*)d_in[10];
    const float* bnm = (const float*)d_in[11];
    const float* Wr  = (const float*)d_in[12];
    const float* br  = (const float*)d_in[13];
    const float* gr  = (const float*)d_in[14];
    const float* brn = (const float*)d_in[15];
    float* out = (float*)d_out;

    void *pH0,*pH1,*pH2,*pW,*pO,*pB,*pEw0,*pEint,*pEcsr;
    void *pR0,*pR1,*pR2,*pR3;
    void *pP1,*pP2,*pP3,*pQ1,*pQ2,*pQ3,*pD0,*pD1,*pD2,*pD3,*pEc;
    cudaGetSymbolAddress(&pH0, g_h0);  cudaGetSymbolAddress(&pH1, g_h1);
    cudaGetSymbolAddress(&pH2, g_h2);  cudaGetSymbolAddress(&pW, g_w);
    cudaGetSymbolAddress(&pO, g_o);    cudaGetSymbolAddress(&pB, g_bb);
    cudaGetSymbolAddress(&pEw0, g_ew0);
    cudaGetSymbolAddress(&pEint, g_eint); cudaGetSymbolAddress(&pEcsr, g_ecsr);
    cudaGetSymbolAddress(&pR0, g_rp0); cudaGetSymbolAddress(&pR1, g_rp1);
    cudaGetSymbolAddress(&pR2, g_rp2); cudaGetSymbolAddress(&pR3, g_rp3);
    cudaGetSymbolAddress(&pP1, g_perm1); cudaGetSymbolAddress(&pP2, g_perm2);
    cudaGetSymbolAddress(&pP3, g_perm3);
    cudaGetSymbolAddress(&pQ1, g_pos1);  cudaGetSymbolAddress(&pQ2, g_pos2);
    cudaGetSymbolAddress(&pQ3, g_pos3);
    cudaGetSymbolAddress(&pD0, g_deg0);  cudaGetSymbolAddress(&pD1, g_deg1);
    cudaGetSymbolAddress(&pD2, g_deg2);  cudaGetSymbolAddress(&pD3, g_deg3);
    cudaGetSymbolAddress(&pEc, g_ecnt);

    float* h0=(float*)pH0; float* h1=(float*)pH1; float* h2=(float*)pH2;
    float* wb=(float*)pW;  float* o =(float*)pO;  float* b =(float*)pB;
    float* ew0=(float*)pEw0;
    int4* eint=(int4*)pEint;
    int4* ein1=eint; int4* ein2=eint+EE; int4* ein3=eint+2*EE;
    int4* ecsr=(int4*)pEcsr;
    int4* cs0=ecsr; int4* cs1=ecsr+EE; int4* cs2=ecsr+2*EE; int4* cs3=ecsr+3*EE;
    int* rp0=(int*)pR0; int* rp1=(int*)pR1; int* rp2=(int*)pR2; int* rp3=(int*)pR3;
    int* perm1=(int*)pP1;  int* perm2=(int*)pP2;  int* perm3=(int*)pP3;
    int* pos1=(int*)pQ1;   int* pos2=(int*)pQ2;   int* pos3=(int*)pQ3;
    float* deg0=(float*)pD0; float* deg1=(float*)pD1;
    float* deg2=(float*)pD2; float* deg3=(float*)pD3;
    int* ecnt=(int*)pEc;
    const int* src0 = ei;
    const int* dst0 = ei + EE;
    const float* NUF = nullptr;
    const int* NUI = nullptr;
    const int4* NU4 = nullptr;

    dim3 cgrid(GRID_COOP), cblk(256);

    // ---- mega0: init + edge embed + norm + deg + scan + fill ----
    {
        void* args[] = { (void*)&ea, (void*)&Wew, (void*)&Web,
                         (void*)&src0, (void*)&dst0, (void*)&rp0 };
        cudaLaunchCooperativeKernel((void*)k_mega0, cgrid, cblk, args, 0, 0);
    }

    // ---- GCN0 ----
    k_mm<<<cdiv(NN,128),256>>>(x, Wd, wb, gn, bnm, NUI, NUI, NUF, 0, NN);
    {
        int u2 = 0;
        k_gather<<<cdiv(NN*32,256),256>>>(rp0, cs0, u2, wb, h0, NN, Wp, bd, deg0, 1.f);
    }

    // ---- pool1 + GCN1 ----
    {
        int n = NN, k = L1N, fix = EE; const int* dyn = nullptr; int* ec = ecnt + 0;
        void* args[] = { &n, &k, (void*)&src0, (void*)&dst0, (void*)&ew0, (void*)&NU4,
                         &fix, (void*)&dyn,
                         &perm1, &pos1, &deg1, &ec, &ein1, &cs1, &rp1 };
        cudaLaunchCooperativeKernel((void*)k_mega, cgrid, cblk, args, 0, 0);
    }
    k_mm<<<cdiv(L1N,128),256>>>(h0, Wd+HD*HD, wb, gn+HD, bnm+HD, perm1, NUI, NUF, 0, L1N);
    {
        int u2 = 0;
        k_gather<<<cdiv(L1N*32,256),256>>>(rp1, cs1, u2, wb, h1, L1N, Wp+HD,
                                           bd+HD, deg1, 1.f);
    }

    // ---- pool2 + GCN2 ----
    {
        int n = L1N, k = L2N, fix = 0; const int* dyn = ecnt + 0; int* ec = ecnt + 1;
        void* args[] = { &n, &k, (void*)&NUI, (void*)&NUI, (void*)&NUF, (void*)&ein1,
                         &fix, (void*)&dyn,
                         &perm2, &pos2, &deg2, &ec, &ein2, &cs2, &rp2 };
        cudaLaunchCooperativeKernel((void*)k_mega, cgrid, cblk, args, 0, 0);
    }
    k_mm<<<cdiv(L2N,128),256>>>(h1, Wd+2*HD*HD, wb, gn+2*HD, bnm+2*HD, perm2, NUI, NUF, 0, L2N);
    {
        int u2 = 0;
        k_gather<<<cdiv(L2N*32,256),256>>>(rp2, cs2, u2, wb, h2, L2N, Wp+2*HD,
                                           bd+2*HD, deg2, 1.f);
    }

    // ---- pool3 + GCN3 (bottom) ----
    {
        int n = L2N, k = L3N, fix = 0; const int* dyn = ecnt + 1; int* ec = ecnt + 2;
        void* args[] = { &n, &k, (void*)&NUI, (void*)&NUI, (void*)&NUF, (void*)&ein2,
                         &fix, (void*)&dyn,
                         &perm3, &pos3, &deg3, &ec, &ein3, &cs3, &rp3 };
        cudaLaunchCooperativeKernel((void*)k_mega, cgrid, cblk, args, 0, 0);
    }
    k_mm<<<cdiv(L3N,128),256>>>(h2, Wd+3*HD*HD, wb, gn+3*HD, bnm+3*HD, perm3, NUI, NUF, 0, L3N);
    {
        int u2 = 0;
        k_gather<<<cdiv(L3N*32,256),256>>>(rp3, cs3, u2, wb, o, L3N, NUF,
                                           bd+3*HD, deg3, 1.f);
    }

    // ---- up 0 (n=12500): res=h2, unpool o (no lrelu on u) -> b ----
    k_mm<<<cdiv(L2N,128),256>>>(h2, Wu, wb, NUF, NUF, NUI, pos3, o, 0, L2N);
    {
        int u2 = 1;
        k_gather<<<cdiv(L2N*32,256),256>>>(rp2, cs2, u2, wb, b, L2N, NUF,
                                           bu, deg2, 2.f);
    }

    // ---- up 1 (n=25000): res=h1, unpool lrelu(b) -> o ----
    k_mm<<<cdiv(L1N,128),256>>>(h1, Wu+HD*HD, wb, NUF, NUF, NUI, pos2, b, 1, L1N);
    {
        int u2 = 1;
        k_gather<<<cdiv(L1N*32,256),256>>>(rp1, cs1, u2, wb, o, L1N, NUF,
                                           bu+HD, deg1, 2.f);
    }

    // ---- up 2 (n=50000): res=h0, unpool lrelu(o) -> b ----
    k_mm<<<cdiv(NN,128),256>>>(h0, Wu+2*HD*HD, wb, NUF, NUF, NUI, pos1, o, 1, NN);
    {
        int u2 = 1;
        k_gather<<<cdiv(NN*32,256),256>>>(rp0, cs0, u2, wb, b, NN, NUF,
                                          bu+2*HD, deg0, 2.f);
    }

    // ---- readout (g_gsum zeroed in mega0) ----
    k_colsum<<<cdiv(NN,256),128>>>(b, NN);
    k_final<<<1,128>>>(Wr, br, gr, brn, out, out_size);
}

// round 14
// speedup vs baseline: 1.2066x; 1.2066x over previous
#include <cuda_runtime.h>
#include <cooperative_groups.h>
#include <stdint.h>
namespace cg = cooperative_groups;

#define NN 50000
#define L1N 25000
#define L2N 12500
#define L3N 6250
#define EE 800000
#define HD 128
#define BNS 0.9999950000374997f
#define GRID_COOP 296

static inline int cdiv(int a, int b){ return (a + b - 1) / b; }

// ------------------------- streams for fork/join overlap (pre-main init) --------------
struct HxStreams {
    cudaStream_t sB;
    cudaEvent_t evF, evJ;
    HxStreams(){
        cudaStreamCreateWithFlags(&sB, cudaStreamNonBlocking);
        cudaEventCreateWithFlags(&evF, cudaEventDisableTiming);
        cudaEventCreateWithFlags(&evJ, cudaEventDisableTiming);
    }
};
static HxStreams g_hx;

// ------------------------- device scratch (static, no allocs) -------------------------
__device__ float g_h0[(size_t)NN*HD];
__device__ float g_h1[(size_t)L1N*HD];
__device__ float g_h2[(size_t)L2N*HD];
__device__ float g_w [(size_t)NN*HD];
__device__ float g_o [(size_t)NN*HD];
__device__ float g_bb[(size_t)NN*HD];
__device__ float g_ew0[EE];
__device__ int   g_srcl[3][EE];
__device__ int   g_dstl[3][EE];
__device__ float g_ewl[3][EE];
__device__ int   g_csrc[4][EE];
__device__ float g_cc1[4][EE];
__device__ float g_cc2[4][EE];
__device__ int   g_rp0[NN+1];
__device__ int   g_rp1[L1N+1];
__device__ int   g_rp2[L2N+1];
__device__ int   g_rp3[L3N+1];
__device__ int   g_cur[NN];
__device__ int   g_cnt[NN];
__device__ int   g_bsum[64];
__device__ float g_dv1[NN];
__device__ float g_dv2[NN];
__device__ float g_deg0[NN];
__device__ float g_deg1[L1N];
__device__ float g_deg2[L2N];
__device__ float g_deg3[L3N];
__device__ float g_s[NN];
__device__ unsigned g_u[NN];
__device__ int g_perm1[L1N];
__device__ int g_perm2[L2N];
__device__ int g_perm3[L3N];
__device__ int g_pos1[NN];
__device__ int g_pos2[L1N];
__device__ int g_pos3[L2N];
__device__ unsigned g_hist0[2048];
__device__ unsigned g_hist1[2048];
__device__ unsigned g_hist2[1024];
__device__ unsigned g_mn, g_mx;
__device__ unsigned g_thr;
__device__ int g_T;
__device__ unsigned g_selP;
__device__ int g_selK;
__device__ int g_pcnt, g_eqcnt;
__device__ int g_ecnt[3];
__device__ float g_gsum[HD];

// ------------------------- helpers -------------------------
__device__ __forceinline__ unsigned fenc(float f){
    unsigned u = __float_as_uint(f);
    return (u & 0x80000000u) ? ~u : (u | 0x80000000u);
}
__device__ __forceinline__ float fdec(unsigned u){
    return __uint_as_float((u & 0x80000000u) ? (u ^ 0x80000000u) : ~u);
}
__device__ __forceinline__ unsigned long long dup2(float x){
    unsigned long long r; unsigned u = __float_as_uint(x);
    asm("mov.b64 %0, {%1, %1};" : "=l"(r) : "r"(u));
    return r;
}
#define FMA2(d, a, b) asm("fma.rn.f32x2 %0, %1, %2, %0;" : "+l"(d) : "l"(a), "l"(b))
__device__ __forceinline__ float lrelu1(float v){ return v > 0.f ? v : 0.01f * v; }
__device__ __forceinline__ float4 lrelu4(float4 v){
    v.x = lrelu1(v.x); v.y = lrelu1(v.y); v.z = lrelu1(v.z); v.w = lrelu1(v.w);
    return v;
}

// ------------------------- init -------------------------
__global__ void k_init(){
    int i = blockIdx.x * blockDim.x + threadIdx.x;
    if (i < 2048){ g_hist0[i] = 0u; g_hist1[i] = 0u; }
    if (i < 1024) g_hist2[i] = 0u;
    if (i < HD) g_gsum[i] = 0.f;
    if (i == 0){ g_mn = 0xFFFFFFFFu; g_mx = 0u; }
    if (i < NN){ g_deg0[i] = 0.f; g_cnt[i] = 0; }
}

// ------------------------- edge embedding + min/max -------------------------
__global__ void k_ew(const float* __restrict__ ea, const float* __restrict__ ww,
                     const float* __restrict__ wb){
    int e = blockIdx.x * blockDim.x + threadIdx.x;
    bool inb = e < EE;
    float acc = 0.f;
    if (inb){
        acc = wb[0];
        const float4* a4 = (const float4*)(ea + (size_t)e * 16);
        const float4* w4 = (const float4*)ww;
        #pragma unroll
        for (int j = 0; j < 4; j++){
            float4 a = a4[j], w = w4[j];
            acc += a.x*w.x + a.y*w.y + a.z*w.z + a.w*w.w;
        }
        g_ew0[e] = acc;
    }
    unsigned em = inb ? fenc(acc) : 0xFFFFFFFFu;
    unsigned eM = inb ? fenc(acc) : 0u;
    __shared__ unsigned smn[256], smx[256];
    smn[threadIdx.x] = em; smx[threadIdx.x] = eM;
    __syncthreads();
    for (int s = 128; s > 0; s >>= 1){
        if (threadIdx.x < s){
            smn[threadIdx.x] = min(smn[threadIdx.x], smn[threadIdx.x + s]);
            smx[threadIdx.x] = max(smx[threadIdx.x], smx[threadIdx.x + s]);
        }
        __syncthreads();
    }
    if (threadIdx.x == 0){ atomicMin(&g_mn, smn[0]); atomicMax(&g_mx, smx[0]); }
}

__global__ void k_ewfin(const int* __restrict__ dst0){
    int e = blockIdx.x * blockDim.x + threadIdx.x;
    if (e >= EE) return;
    float mn = fdec(g_mn), mx = fdec(g_mx);
    float w = (g_ew0[e] - mn) / ((mx - mn) + 1e-7f);
    g_ew0[e] = w;
    int d = dst0[e];
    atomicAdd(&g_deg0[d], w);
    atomicAdd(&g_cnt[d], 1);
}

// ------------------------- multi-block scan (tile=4096, plain kernels) ----------------
__global__ void __launch_bounds__(1024) k_scanA(int n){
    __shared__ int wsum[32];
    int tid = threadIdx.x;
    int lane = tid & 31, w = tid >> 5;
    int tile0 = blockIdx.x * 4096;
    int sum = 0;
    #pragma unroll
    for (int j = 0; j < 4; j++){
        int i = tile0 + j * 1024 + tid;
        if (i < n) sum += g_cnt[i];
    }
    #pragma unroll
    for (int off = 16; off > 0; off >>= 1)
        sum += __shfl_xor_sync(0xffffffffu, sum, off);
    if (lane == 0) wsum[w] = sum;
    __syncthreads();
    if (tid < 32){
        int v = wsum[tid];
        #pragma unroll
        for (int off = 16; off > 0; off >>= 1)
            v += __shfl_xor_sync(0xffffffffu, v, off);
        if (tid == 0) g_bsum[blockIdx.x] = v;
    }
}

__global__ void __launch_bounds__(1024) k_scanB(const float* __restrict__ deg, int n,
                                                int* __restrict__ rp, int nblocks){
    __shared__ int tile[4096];
    __shared__ int wsum[32];
    __shared__ int sOff;
    int tid = threadIdx.x;
    int lane = tid & 31, w = tid >> 5;
    int tile0 = blockIdx.x * 4096;

    if (tid < 32){
        int v = (tid < nblocks && tid < blockIdx.x) ? g_bsum[tid] : 0;
        #pragma unroll
        for (int off = 16; off > 0; off >>= 1)
            v += __shfl_xor_sync(0xffffffffu, v, off);
        if (tid == 0) sOff = v;
    }
    #pragma unroll
    for (int j = 0; j < 4; j++){
        int i = tile0 + j * 1024 + tid;
        tile[j * 1024 + tid] = (i < n) ? g_cnt[i] : 0;
    }
    __syncthreads();

    int base = tid * 4;
    int a0 = tile[base], a1 = tile[base+1], a2 = tile[base+2], a3 = tile[base+3];
    int tsum = a0 + a1 + a2 + a3;
    int x = tsum;
    #pragma unroll
    for (int off = 1; off < 32; off <<= 1){
        int t = __shfl_up_sync(0xffffffffu, x, off);
        if (lane >= off) x += t;
    }
    if (lane == 31) wsum[w] = x;
    __syncthreads();
    if (w == 0){
        int y = wsum[lane];
        #pragma unroll
        for (int off = 1; off < 32; off <<= 1){
            int t = __shfl_up_sync(0xffffffffu, y, off);
            if (lane >= off) y += t;
        }
        wsum[lane] = y;
    }
    __syncthreads();

    int running = sOff + x - tsum + ((w > 0) ? wsum[w-1] : 0);
    int i0 = tile0 + base;
    int av[4] = { a0, a1, a2, a3 };
    #pragma unroll
    for (int j = 0; j < 4; j++){
        int i = i0 + j;
        if (i < n){
            rp[i] = running;
            g_cur[i] = running;
            float dg = deg[i];
            g_dv1[i] = rsqrtf(dg + 1.f);
            g_dv2[i] = rsqrtf(dg + 2.f);
            running += av[j];
            if (i == n - 1) rp[n] = running;
        }
    }
}

// ------------------------- CSR fill -------------------------
__global__ void k_fill(const int* __restrict__ s, const int* __restrict__ d,
                       const float* __restrict__ w, int fixedcnt,
                       const int* __restrict__ dyncnt,
                       int* __restrict__ csrc, float* __restrict__ cc1,
                       float* __restrict__ cc2){
    int cnt = dyncnt ? *dyncnt : fixedcnt;
    for (int e = blockIdx.x * blockDim.x + threadIdx.x; e < cnt;
         e += gridDim.x * blockDim.x){
        int a = s[e], b = d[e];
        float we = w[e];
        int slot = atomicAdd(&g_cur[b], 1);
        csrc[slot] = a;
        cc1[slot] = g_dv1[a] * we * g_dv1[b];
        cc2[slot] = g_dv2[a] * we * g_dv2[b];
    }
}

// ------------------------- relabel (plain) -------------------------
__global__ void k_relabel(const int* __restrict__ s, const int* __restrict__ d,
                          const float* __restrict__ w, const int* __restrict__ pos,
                          int* __restrict__ ns, int* __restrict__ nd, float* __restrict__ nw,
                          float* __restrict__ degn, int* __restrict__ ecnt,
                          int fixedcnt, const int* __restrict__ dyncnt){
    int cnt = dyncnt ? *dyncnt : fixedcnt;
    for (int e = blockIdx.x * blockDim.x + threadIdx.x; e < cnt;
         e += gridDim.x * blockDim.x){
        int a = pos[s[e]], b2 = pos[d[e]];
        if (a >= 0 && b2 >= 0){
            int j = atomicAdd(ecnt, 1);
            float we = w[e];
            ns[j] = a; nd[j] = b2; nw[j] = we;
            atomicAdd(&degn[b2], we);
            atomicAdd(&g_cnt[b2], 1);
        }
    }
}

// ------------------------- radix-select helper -------------------------
__device__ __forceinline__ void warp_sel(const unsigned* A, int nbins, int k,
                                         unsigned* outBin, int* outKrem){
    int lane = threadIdx.x & 31;
    int chunk = nbins >> 5;
    int base = nbins - 1 - lane * chunk;
    unsigned cnt = 0;
    for (int j = 0; j < chunk; j++) cnt += A[base - j];
    unsigned pre = cnt;
    #pragma unroll
    for (int off = 1; off < 32; off <<= 1){
        unsigned t = __shfl_up_sync(0xffffffffu, pre, off);
        if (lane >= off) pre += t;
    }
    pre -= cnt;
    bool sel = (pre < (unsigned)k) && ((unsigned)k <= pre + cnt);
    unsigned m = __ballot_sync(0xffffffffu, sel);
    int L = __ffs(m) - 1;
    unsigned bin = 0; int krem = 0;
    if (lane == L){
        unsigned run = pre;
        for (int j = 0; j < chunk; j++){
            int b = base - j;
            unsigned c = A[b];
            if (run + c >= (unsigned)k){ bin = (unsigned)b; krem = k - (int)run; break; }
            run += c;
        }
    }
    bin  = __shfl_sync(0xffffffffu, bin, L);
    krem = __shfl_sync(0xffffffffu, krem, L);
    *outBin = bin; *outKrem = krem;
}

// ------------------------- cooperative pool: hist passes + selects + partition --------
__global__ void __launch_bounds__(256) k_pool(int n, int k,
        int* __restrict__ perm, int* __restrict__ pos, float* __restrict__ degn,
        int* __restrict__ ecnt){
    cg::grid_group grid = cg::this_grid();
    __shared__ unsigned sh[2048];
    int tid = threadIdx.x, bid = blockIdx.x;
    int gs = gridDim.x * blockDim.x, gtid = bid * blockDim.x + tid;

    // S0: grid-wide pass-0 histogram -> g_hist0 (pre-zeroed)
    for (int i = tid; i < 2048; i += 256) sh[i] = 0u;
    __syncthreads();
    for (int i = gtid; i < n; i += gs) atomicAdd(&sh[g_u[i] >> 21], 1u);
    __syncthreads();
    for (int i = tid; i < 2048; i += 256){
        unsigned c = sh[i];
        if (c) atomicAdd(&g_hist0[i], c);
    }
    grid.sync();

    // S1: block0 select pass 0
    if (bid == 0 && tid < 32){
        unsigned b; int kr;
        warp_sel(g_hist0, 2048, k, &b, &kr);
        if (tid == 0){ g_selP = b; g_selK = kr; }
    }
    grid.sync();

    // S2: grid-wide pass-1 histogram -> g_hist1 ; zero g_hist0
    {
        unsigned p0 = g_selP;
        for (int i = tid; i < 2048; i += 256) sh[i] = 0u;
        __syncthreads();
        for (int i = gtid; i < n; i += gs){
            unsigned ui = g_u[i];
            if ((ui >> 21) == p0) atomicAdd(&sh[(ui >> 10) & 2047u], 1u);
        }
        __syncthreads();
        for (int i = tid; i < 2048; i += 256){
            unsigned c = sh[i];
            if (c) atomicAdd(&g_hist1[i], c);
        }
        for (int i = gtid; i < 2048; i += gs) g_hist0[i] = 0u;
    }
    grid.sync();

    // S3: block0 select pass 1
    if (bid == 0 && tid < 32){
        unsigned p0 = g_selP;
        unsigned b; int kr;
        warp_sel(g_hist1, 2048, g_selK, &b, &kr);
        if (tid == 0){ g_selP = (p0 << 11) | b; g_selK = kr; }
    }
    grid.sync();

    // S4: grid-wide pass-2 histogram -> g_hist2 ; zero g_hist1
    {
        unsigned p1 = g_selP;
        for (int i = tid; i < 1024; i += 256) sh[i] = 0u;
        __syncthreads();
        for (int i = gtid; i < n; i += gs){
            unsigned ui = g_u[i];
            if ((ui >> 10) == p1) atomicAdd(&sh[ui & 1023u], 1u);
        }
        __syncthreads();
        for (int i = tid; i < 1024; i += 256){
            unsigned c = sh[i];
            if (c) atomicAdd(&g_hist2[i], c);
        }
        for (int i = gtid; i < 2048; i += gs) g_hist1[i] = 0u;
    }
    grid.sync();

    // S5: block0 select pass 2 -> threshold + reset counters
    if (bid == 0 && tid < 32){
        unsigned p1 = g_selP;
        unsigned b; int kr;
        warp_sel(g_hist2, 1024, g_selK, &b, &kr);
        if (tid == 0){
            g_thr = (p1 << 10) | b; g_T = kr;
            g_pcnt = 0; g_eqcnt = 0; *ecnt = 0;
        }
    }
    grid.sync();

    // P3: partition + zero child deg/cnt + zero g_hist2 for next level
    {
        unsigned ut = g_thr; int T = g_T;
        for (int i = gtid; i < 1024; i += gs) g_hist2[i] = 0u;
        for (int i = gtid; i < k; i += gs){ degn[i] = 0.f; g_cnt[i] = 0; }
        for (int i = gtid; i < n; i += gs){
            unsigned ui = g_u[i];
            int p = -1;
            if (ui > ut) p = atomicAdd(&g_pcnt, 1);
            else if (ui == ut){
                int t = atomicAdd(&g_eqcnt, 1);
                if (t < T) p = atomicAdd(&g_pcnt, 1);
            }
            pos[i] = p;
            if (p >= 0) perm[p] = i;
        }
    }
}

// ------------------------- fused GEMM (writes C only) -------------------------
__global__ void __launch_bounds__(256, 2) k_mm(
        const float* __restrict__ A, const float* __restrict__ W,
        float* __restrict__ C,
        const float* __restrict__ bns, const float* __restrict__ bnb,
        const int* __restrict__ perm,
        const int* __restrict__ pos, const float* __restrict__ uu, int uflag, int n){
    __shared__ __align__(16) float As[16][132];
    __shared__ __align__(16) float Bs[16][128];
    int tid = threadIdx.x;
    int tx = tid & 15, ty = tid >> 4;
    int bm0 = blockIdx.x * 128;
    unsigned long long acc[4][8];
    #pragma unroll
    for (int p = 0; p < 4; p++)
        #pragma unroll
        for (int c = 0; c < 8; c++) acc[p][c] = 0ull;

    for (int k0 = 0; k0 < 128; k0 += 16){
        #pragma unroll
        for (int i = 0; i < 2; i++){
            int idx = tid + i * 256;
            int r = idx >> 2, c4 = idx & 3;
            int grow = bm0 + r;
            float4 v = make_float4(0.f, 0.f, 0.f, 0.f);
            if (grow < n){
                if (perm){
                    int old = perm[grow];
                    v = lrelu4(*(const float4*)(A + (size_t)old * 128 + k0 + c4 * 4));
                    float sc = g_s[old];
                    float4 s4 = *(const float4*)(bns + k0 + c4 * 4);
                    float4 o4 = *(const float4*)(bnb + k0 + c4 * 4);
                    v.x = v.x * sc * (s4.x * BNS) + o4.x;
                    v.y = v.y * sc * (s4.y * BNS) + o4.y;
                    v.z = v.z * sc * (s4.z * BNS) + o4.z;
                    v.w = v.w * sc * (s4.w * BNS) + o4.w;
                } else if (pos){
                    v = lrelu4(*(const float4*)(A + (size_t)grow * 128 + k0 + c4 * 4));
                    int pr = pos[grow];
                    if (pr >= 0){
                        float4 uv = *(const float4*)(uu + (size_t)pr * 128 + k0 + c4 * 4);
                        if (uflag) uv = lrelu4(uv);
                        v.x += uv.x; v.y += uv.y; v.z += uv.z; v.w += uv.w;
                    }
                } else {
                    v = *(const float4*)(A + (size_t)grow * 128 + k0 + c4 * 4);
                    if (bns){
                        float4 s4 = *(const float4*)(bns + k0 + c4 * 4);
                        float4 o4 = *(const float4*)(bnb + k0 + c4 * 4);
                        v.x = v.x * (s4.x * BNS) + o4.x;
                        v.y = v.y * (s4.y * BNS) + o4.y;
                        v.z = v.z * (s4.z * BNS) + o4.z;
                        v.w = v.w * (s4.w * BNS) + o4.w;
                    }
                }
            }
            As[c4*4+0][r] = v.x; As[c4*4+1][r] = v.y;
            As[c4*4+2][r] = v.z; As[c4*4+3][r] = v.w;
        }
        #pragma unroll
        for (int i = 0; i < 2; i++){
            int idx = tid + i * 256;
            int kk = idx >> 5, c = idx & 31;
            *(float4*)&Bs[kk][c*4] = *(const float4*)(W + (size_t)(k0 + kk) * 128 + c * 4);
        }
        __syncthreads();
        #pragma unroll
        for (int kk = 0; kk < 16; kk++){
            ulonglong2 aA = *(const ulonglong2*)&As[kk][ty*8];
            ulonglong2 aB = *(const ulonglong2*)&As[kk][ty*8+4];
            float4 b0 = *(const float4*)&Bs[kk][tx*8];
            float4 b1 = *(const float4*)&Bs[kk][tx*8+4];
            unsigned long long ap[4] = { aA.x, aA.y, aB.x, aB.y };
            unsigned long long bb[8] = { dup2(b0.x), dup2(b0.y), dup2(b0.z), dup2(b0.w),
                                         dup2(b1.x), dup2(b1.y), dup2(b1.z), dup2(b1.w) };
            #pragma unroll
            for (int p = 0; p < 4; p++)
                #pragma unroll
                for (int c = 0; c < 8; c++)
                    FMA2(acc[p][c], ap[p], bb[c]);
        }
        __syncthreads();
    }
    #pragma unroll
    for (int p = 0; p < 4; p++){
        #pragma unroll
        for (int j = 0; j < 2; j++){
            int row = bm0 + ty*8 + 2*p + j;
            if (row >= n) continue;
            float vals[8];
            #pragma unroll
            for (int c = 0; c < 8; c++){
                unsigned long long u = acc[p][c];
                vals[c] = j ? __uint_as_float((unsigned)(u >> 32))
                            : __uint_as_float((unsigned)u);
            }
            *(float4*)(C + (size_t)row * 128 + tx*8)     =
                make_float4(vals[0], vals[1], vals[2], vals[3]);
            *(float4*)(C + (size_t)row * 128 + tx*8 + 4) =
                make_float4(vals[4], vals[5], vals[6], vals[7]);
        }
    }
}

// ------------- CSR gather + self-loop epilogue (+ fused score) ------------------------
__global__ void k_gather(const int* __restrict__ rp, const int* __restrict__ csrc,
                         const float* __restrict__ cc, const float* __restrict__ C,
                         float* __restrict__ out, int n, const float* __restrict__ p,
                         const float* __restrict__ bias, const float* __restrict__ deg,
                         float fill){
    int wid = (blockIdx.x * blockDim.x + threadIdx.x) >> 5;
    int lane = threadIdx.x & 31;
    if (wid >= n) return;
    int beg = rp[wid], end = rp[wid + 1];
    float4 acc = make_float4(0.f, 0.f, 0.f, 0.f);
    int e = beg;
    for (; e + 1 < end; e += 2){
        int s0 = csrc[e], s1 = csrc[e+1];
        float c0 = cc[e], c1 = cc[e+1];
        float4 v0 = *(const float4*)(C + (size_t)s0 * 128 + lane * 4);
        float4 v1 = *(const float4*)(C + (size_t)s1 * 128 + lane * 4);
        acc.x += c0*v0.x + c1*v1.x;
        acc.y += c0*v0.y + c1*v1.y;
        acc.z += c0*v0.z + c1*v1.z;
        acc.w += c0*v0.w + c1*v1.w;
    }
    if (e < end){
        int s0 = csrc[e];
        float c0 = cc[e];
        float4 v0 = *(const float4*)(C + (size_t)s0 * 128 + lane * 4);
        acc.x += c0*v0.x; acc.y += c0*v0.y; acc.z += c0*v0.z; acc.w += c0*v0.w;
    }
    float4 cr = *(const float4*)(C + (size_t)wid * 128 + lane * 4);
    float sc = fill / (deg[wid] + fill);
    float4 b4 = *(const float4*)(bias + lane * 4);
    float4 o;
    o.x = acc.x + sc * cr.x + b4.x;
    o.y = acc.y + sc * cr.y + b4.y;
    o.z = acc.z + sc * cr.z + b4.z;
    o.w = acc.w + sc * cr.w + b4.w;
    *(float4*)(out + (size_t)wid * 128 + lane * 4) = o;
    if (p){
        float4 pv = *(const float4*)(p + lane * 4);
        float4 hv = lrelu4(o);
        float d = hv.x*pv.x + hv.y*pv.y + hv.z*pv.z + hv.w*pv.w;
        float pp = pv.x*pv.x + pv.y*pv.y + pv.z*pv.z + pv.w*pv.w;
        #pragma unroll
        for (int off = 16; off > 0; off >>= 1){
            d  += __shfl_xor_sync(0xffffffffu, d, off);
            pp += __shfl_xor_sync(0xffffffffu, pp, off);
        }
        if (lane == 0){
            float v = tanhf(d / sqrtf(pp));
            g_s[wid] = v;
            g_u[wid] = fenc(v);
        }
    }
}

// ------------------------- readout -------------------------
__global__ void k_colsum(const float* __restrict__ h, int n){
    int d = threadIdx.x;
    int r0 = blockIdx.x * 256;
    int rend = min(r0 + 256, n);
    float acc = 0.f;
    for (int r = r0; r < rend; r++) acc += h[(size_t)r * 128 + d];
    atomicAdd(&g_gsum[d], acc);
}

__global__ void k_final(const float* __restrict__ Wr, const float* __restrict__ br,
                        const float* __restrict__ gr, const float* __restrict__ brn,
                        float* __restrict__ out, int osz){
    __shared__ float gs[HD];
    int t = threadIdx.x;
    gs[t] = g_gsum[t];
    __syncthreads();
    float acc = br[t];
    for (int d2 = 0; d2 < HD; d2++) acc += gs[d2] * Wr[d2 * HD + t];
    float r = acc * (gr[t] * BNS) + brn[t];
    if (t < osz) out[t] = r;
}

// ------------------------- host orchestration -------------------------
extern "C" void kernel_launch(void* const* d_in, const int* in_sizes, int n_in,
                              void* d_out, int out_size){
    const float* x   = (const float*)d_in[0];
    const int*   ei  = (const int*)d_in[1];
    const float* ea  = (const float*)d_in[2];
    const float* Wew = (const float*)d_in[3];
    const float* Web = (const float*)d_in[4];
    const float* Wd  = (const float*)d_in[5];
    const float* bd  = (const float*)d_in[6];
    const float* Wp  = (const float*)d_in[7];
    const float* Wu  = (const float*)d_in[8];
    const float* bu  = (const float*)d_in[9];
    const float* gn  = (const float*)d_in[10];
    const float* bnm = (const float*)d_in[11];
    const float* Wr  = (const float*)d_in[12];
    const float* br  = (const float*)d_in[13];
    const float* gr  = (const float*)d_in[14];
    const float* brn = (const float*)d_in[15];
    float* out = (float*)d_out;

    void *pH0,*pH1,*pH2,*pW,*pO,*pB,*pEw0,*pSrc,*pDst,*pEwl;
    void *pCs,*pC1,*pC2,*pR0,*pR1,*pR2,*pR3;
    void *pP1,*pP2,*pP3,*pQ1,*pQ2,*pQ3,*pD0,*pD1,*pD2,*pD3,*pEc;
    cudaGetSymbolAddress(&pH0, g_h0);  cudaGetSymbolAddress(&pH1, g_h1);
    cudaGetSymbolAddress(&pH2, g_h2);  cudaGetSymbolAddress(&pW, g_w);
    cudaGetSymbolAddress(&pO, g_o);    cudaGetSymbolAddress(&pB, g_bb);
    cudaGetSymbolAddress(&pEw0, g_ew0);
    cudaGetSymbolAddress(&pSrc, g_srcl); cudaGetSymbolAddress(&pDst, g_dstl);
    cudaGetSymbolAddress(&pEwl, g_ewl);
    cudaGetSymbolAddress(&pCs, g_csrc); cudaGetSymbolAddress(&pC1, g_cc1);
    cudaGetSymbolAddress(&pC2, g_cc2);
    cudaGetSymbolAddress(&pR0, g_rp0); cudaGetSymbolAddress(&pR1, g_rp1);
    cudaGetSymbolAddress(&pR2, g_rp2); cudaGetSymbolAddress(&pR3, g_rp3);
    cudaGetSymbolAddress(&pP1, g_perm1); cudaGetSymbolAddress(&pP2, g_perm2);
    cudaGetSymbolAddress(&pP3, g_perm3);
    cudaGetSymbolAddress(&pQ1, g_pos1);  cudaGetSymbolAddress(&pQ2, g_pos2);
    cudaGetSymbolAddress(&pQ3, g_pos3);
    cudaGetSymbolAddress(&pD0, g_deg0);  cudaGetSymbolAddress(&pD1, g_deg1);
    cudaGetSymbolAddress(&pD2, g_deg2);  cudaGetSymbolAddress(&pD3, g_deg3);
    cudaGetSymbolAddress(&pEc, g_ecnt);

    float* h0=(float*)pH0; float* h1=(float*)pH1; float* h2=(float*)pH2;
    float* wb=(float*)pW;  float* o =(float*)pO;  float* b =(float*)pB;
    float* ew0=(float*)pEw0;
    int* srcB=(int*)pSrc; int* dstB=(int*)pDst; float* ewB=(float*)pEwl;
    int* src1=srcB;        int* dst1=dstB;        float* ew1=ewB;
    int* src2=srcB+EE;     int* dst2=dstB+EE;     float* ew2=ewB+EE;
    int* src3=srcB+2*EE;   int* dst3=dstB+2*EE;   float* ew3=ewB+2*EE;
    int* csrc=(int*)pCs; float* cc1=(float*)pC1; float* cc2=(float*)pC2;
    int* rp0=(int*)pR0; int* rp1=(int*)pR1; int* rp2=(int*)pR2; int* rp3=(int*)pR3;
    int* perm1=(int*)pP1;  int* perm2=(int*)pP2;  int* perm3=(int*)pP3;
    int* pos1=(int*)pQ1;   int* pos2=(int*)pQ2;   int* pos3=(int*)pQ3;
    float* deg0=(float*)pD0; float* deg1=(float*)pD1;
    float* deg2=(float*)pD2; float* deg3=(float*)pD3;
    int* ecnt=(int*)pEc;
    const int* src0 = ei;
    const int* dst0 = ei + EE;
    const float* NUF = nullptr;
    const int* NUI = nullptr;

    dim3 cgrid(GRID_COOP), cblk(256);
    cudaStream_t sB = g_hx.sB;
    auto fork = [&](){
        cudaEventRecord(g_hx.evF, 0);
        cudaStreamWaitEvent(sB, g_hx.evF, 0);
    };
    auto join = [&](){
        cudaEventRecord(g_hx.evJ, sB);
        cudaStreamWaitEvent(0, g_hx.evJ, 0);
    };

    // ---- setup (main) overlapped with mm0 (sB) ----
    k_init<<<cdiv(NN,256),256>>>();
    fork();
    k_mm<<<cdiv(NN,128),256,0,sB>>>(x, Wd, wb, gn, bnm, NUI, NUI, NUF, 0, NN);
    k_ew<<<cdiv(EE,256),256>>>(ea, Wew, Web);
    k_ewfin<<<cdiv(EE,256),256>>>(dst0);
    int nb0 = cdiv(NN,4096), nb1 = cdiv(L1N,4096), nb2 = cdiv(L2N,4096), nb3 = cdiv(L3N,4096);
    k_scanA<<<nb0,1024>>>(NN);
    k_scanB<<<nb0,1024>>>(deg0, NN, rp0, nb0);
    k_fill<<<2048,256>>>(src0, dst0, ew0, EE, nullptr, csrc, cc1, cc2);
    join();
    k_gather<<<cdiv(NN*32,256),256>>>(rp0, csrc, cc1, wb, h0, NN, Wp, bd, deg0, 1.f);

    // ---- pool1 ; then mm1 (sB) overlapped with csr-build (main) ----
    {
        int n = NN, k = L1N; int* ec = ecnt + 0;
        void* args[] = { &n, &k, &perm1, &pos1, &deg1, &ec };
        cudaLaunchCooperativeKernel((void*)k_pool, cgrid, cblk, args, 0, 0);
    }
    fork();
    k_mm<<<cdiv(L1N,128),256,0,sB>>>(h0, Wd+HD*HD, wb, gn+HD, bnm+HD, perm1, NUI, NUF, 0, L1N);
    k_relabel<<<2048,256>>>(src0, dst0, ew0, pos1, src1, dst1, ew1, deg1, ecnt+0, EE, nullptr);
    k_scanA<<<nb1,1024>>>(L1N);
    k_scanB<<<nb1,1024>>>(deg1, L1N, rp1, nb1);
    k_fill<<<2048,256>>>(src1, dst1, ew1, 0, ecnt+0, csrc+EE, cc1+EE, cc2+EE);
    join();
    k_gather<<<cdiv(L1N*32,256),256>>>(rp1, csrc+EE, cc1+EE, wb, h1, L1N, Wp+HD,
                                       bd+HD, deg1, 1.f);

    // ---- pool2 + GCN2 ----
    {
        int n = L1N, k = L2N; int* ec = ecnt + 1;
        void* args[] = { &n, &k, &perm2, &pos2, &deg2, &ec };
        cudaLaunchCooperativeKernel((void*)k_pool, cgrid, cblk, args, 0, 0);
    }
    fork();
    k_mm<<<cdiv(L2N,128),256,0,sB>>>(h1, Wd+2*HD*HD, wb, gn+2*HD, bnm+2*HD, perm2, NUI, NUF, 0, L2N);
    k_relabel<<<2048,256>>>(src1, dst1, ew1, pos2, src2, dst2, ew2, deg2, ecnt+1, 0, ecnt+0);
    k_scanA<<<nb2,1024>>>(L2N);
    k_scanB<<<nb2,1024>>>(deg2, L2N, rp2, nb2);
    k_fill<<<2048,256>>>(src2, dst2, ew2, 0, ecnt+1, csrc+2*EE, cc1+2*EE, cc2+2*EE);
    join();
    k_gather<<<cdiv(L2N*32,256),256>>>(rp2, csrc+2*EE, cc1+2*EE, wb, h2, L2N, Wp+2*HD,
                                       bd+2*HD, deg2, 1.f);

    // ---- pool3 + GCN3 (bottom) ----
    {
        int n = L2N, k = L3N; int* ec = ecnt + 2;
        void* args[] = { &n, &k, &perm3, &pos3, &deg3, &ec };
        cudaLaunchCooperativeKernel((void*)k_pool, cgrid, cblk, args, 0, 0);
    }
    fork();
    k_mm<<<cdiv(L3N,128),256,0,sB>>>(h2, Wd+3*HD*HD, wb, gn+3*HD, bnm+3*HD, perm3, NUI, NUF, 0, L3N);
    k_relabel<<<2048,256>>>(src2, dst2, ew2, pos3, src3, dst3, ew3, deg3, ecnt+2, 0, ecnt+1);
    k_scanA<<<nb3,1024>>>(L3N);
    k_scanB<<<nb3,1024>>>(deg3, L3N, rp3, nb3);
    k_fill<<<2048,256>>>(src3, dst3, ew3, 0, ecnt+2, csrc+3*EE, cc1+3*EE, cc2+3*EE);
    join();
    k_gather<<<cdiv(L3N*32,256),256>>>(rp3, csrc+3*EE, cc1+3*EE, wb, o, L3N, NUF,
                                       bd+3*HD, deg3, 1.f);

    // ---- up 0 (n=12500): res=h2, unpool o (no lrelu on u) -> b ----
    k_mm<<<cdiv(L2N,128),256>>>(h2, Wu, wb, NUF, NUF, NUI, pos3, o, 0, L2N);
    k_gather<<<cdiv(L2N*32,256),256>>>(rp2, csrc+2*EE, cc2+2*EE, wb, b, L2N, NUF,
                                       bu, deg2, 2.f);

    // ---- up 1 (n=25000): res=h1, unpool lrelu(b) -> o ----
    k_mm<<<cdiv(L1N,128),256>>>(h1, Wu+HD*HD, wb, NUF, NUF, NUI, pos2, b, 1, L1N);
    k_gather<<<cdiv(L1N*32,256),256>>>(rp1, csrc+EE, cc2+EE, wb, o, L1N, NUF,
                                       bu+HD, deg1, 2.f);

    // ---- up 2 (n=50000): res=h0, unpool lrelu(o) -> b ----
    k_mm<<<cdiv(NN,128),256>>>(h0, Wu+2*HD*HD, wb, NUF, NUF, NUI, pos1, o, 1, NN);
    k_gather<<<cdiv(NN*32,256),256>>>(rp0, csrc, cc2, wb, b, NN, NUF,
                                      bu+2*HD, deg0, 2.f);

    // ---- readout ----
    k_colsum<<<cdiv(NN,256),128>>>(b, NN);
    k_final<<<1,128>>>(Wr, br, gr, brn, out, out_size);
}